// round 2
// baseline (speedup 1.0000x reference)
#include <cuda_runtime.h>

constexpr int NB = 4;     // batch
constexpr int C  = 32;
constexpr int H  = 512;
constexpr int W  = 960;
constexpr int Ht = 128;
constexpr int Wt = 240;
constexpr int HW = H * W;

__global__ __launch_bounds__(960, 2)
void tile_warp_cost_kernel(const float* __restrict__ tile_plane,
                           const float* __restrict__ fea_l,
                           const float* __restrict__ fea_r,
                           float* __restrict__ out)
{
    __shared__ float buf[2][W];

    const int tid = threadIdx.x;     // = x, 0..959
    const int y   = blockIdx.x;      // 0..511
    const int b   = blockIdx.y;      // 0..3
    const int x   = tid;

    const int ty = y >> 2, tx = x >> 2;
    const int iy = y & 3,  jx = x & 3;

    // tile_plane [B, 3, Ht, Wt]
    const int tbase  = b * 3 * Ht * Wt + ty * Wt + tx;
    const float d    = __ldg(tile_plane + tbase);
    const float ddx  = __ldg(tile_plane + tbase + Ht * Wt);
    const float ddy  = __ldg(tile_plane + tbase + 2 * Ht * Wt);

    // disparity for the disp_d = 0 hypothesis; all 3 hypotheses share frac weight
    const float disp0 = d + ((float)iy - 1.5f) * ddy + ((float)jx - 1.5f) * ddx;
    const float xs0   = (float)x - disp0;
    const float xf    = floorf(xs0);
    const float w     = xs0 - xf;
    const int   x00   = (int)xf;

    // 4 shared (clamped) tap columns: covers all three hypotheses
    const int j0 = min(max(x00 - 1, 0), W - 1);
    const int j1 = min(max(x00,     0), W - 1);
    const int j2 = min(max(x00 + 1, 0), W - 1);
    const int j3 = min(max(x00 + 2, 0), W - 1);

    // per-pixel validity (uniform over channels) — hoisted out of the loop
    const float wm1 = (float)(W - 1);
    const bool vM = (xs0 + 1.0f >= 0.0f) && (xs0 + 1.0f <= wm1);
    const bool v0 = (xs0        >= 0.0f) && (xs0        <= wm1);
    const bool vP = (xs0 - 1.0f >= 0.0f) && (xs0 - 1.0f <= wm1);

    const float* frp = fea_r + (size_t)(b * C * H + y) * W;
    const float* flp = fea_l + (size_t)(b * C * H + y) * W + x;

    // prefetch channel 0
    float4 rv = make_float4(0.f, 0.f, 0.f, 0.f);
    if (tid < 240) rv = __ldg((const float4*)frp + tid);
    float fl = __ldg(flp);

    float cM = 0.f, c0 = 0.f, cP = 0.f, sA = 0.f;

    #pragma unroll 2
    for (int c = 0; c < C; ++c) {
        float* bc = buf[c & 1];
        if (tid < 240) ((float4*)bc)[tid] = rv;   // stage current channel row
        __syncthreads();                          // row visible to all

        const float flc = fl;
        if (c + 1 < C) {                          // prefetch next channel
            frp += HW; flp += HW;
            if (tid < 240) rv = __ldg((const float4*)frp + tid);
            fl = __ldg(flp);
        }

        const float r0 = bc[j0], r1 = bc[j1], r2 = bc[j2], r3 = bc[j3];
        const float wP = fmaf(w, r1 - r0, r0);    // disp_d = +1
        const float w0 = fmaf(w, r2 - r1, r1);    // disp_d =  0
        const float wM = fmaf(w, r3 - r2, r2);    // disp_d = -1

        cM += fabsf(flc - wM);
        c0 += fabsf(flc - w0);
        cP += fabsf(flc - wP);
        sA += fabsf(flc);                         // fallback for invalid hypotheses
        // no trailing barrier needed: buf[c&1] is next written at iter c+2,
        // and all reads of it complete before iter c+1's barrier.
    }

    if (!vM) cM = sA;
    if (!v0) c0 = sA;
    if (!vP) cP = sA;

    // output [B, 48, Ht, Wt]; channel = vblock*16 + iy*4 + jx; vblock order: -1, 0, +1
    const int chsp  = (iy * 4 + jx) * (Ht * Wt);
    const int obase = b * 48 * Ht * Wt + ty * Wt + tx;
    out[obase + chsp]                = cM;
    out[obase + 16 * Ht * Wt + chsp] = c0;
    out[obase + 32 * Ht * Wt + chsp] = cP;
}

extern "C" void kernel_launch(void* const* d_in, const int* in_sizes, int n_in,
                              void* d_out, int out_size)
{
    const float* tile_plane = (const float*)d_in[0];
    const float* fea_l      = (const float*)d_in[1];
    const float* fea_r      = (const float*)d_in[2];
    float*       out        = (float*)d_out;

    dim3 grid(H, NB);     // (512, 4)
    dim3 block(960);
    tile_warp_cost_kernel<<<grid, block>>>(tile_plane, fea_l, fea_r, out);
}

// round 3
// speedup vs baseline: 1.1307x; 1.1307x over previous
#include <cuda_runtime.h>
#include <cstdint>

constexpr int NB = 4;
constexpr int C  = 32;
constexpr int H  = 512;
constexpr int W  = 960;
constexpr int Ht = 128;
constexpr int Wt = 240;
constexpr int HW = H * W;

constexpr int WPB = 5;     // warps per block
constexpr int PXW = 64;    // pixels per warp (2 per lane, strided by 32)
constexpr int WIN = 128;   // fea_r window floats per warp
constexpr int STG = WIN + PXW;  // 192 floats per pipeline stage (window + fea_l)
constexpr int D   = 4;     // pipeline depth (channels in flight)

__device__ __forceinline__ void cp16(uint32_t s, const void* g, bool pred) {
    asm volatile(
        "{ .reg .pred p; setp.ne.b32 p, %2, 0;\n"
        "  @p cp.async.cg.shared.global [%0], [%1], 16; }\n"
        :: "r"(s), "l"(g), "r"((int)pred) : "memory");
}
__device__ __forceinline__ void cp_commit() {
    asm volatile("cp.async.commit_group;" ::: "memory");
}
template<int N>
__device__ __forceinline__ void cp_wait() {
    asm volatile("cp.async.wait_group %0;" :: "n"(N) : "memory");
}

__global__ __launch_bounds__(32 * WPB, 8)
void tile_warp_cost_kernel(const float* __restrict__ tile_plane,
                           const float* __restrict__ fea_l,
                           const float* __restrict__ fea_r,
                           float* __restrict__ out)
{
    __shared__ __align__(16) float ring[WPB][D][STG];

    const int wid  = threadIdx.x >> 5;
    const int lane = threadIdx.x & 31;
    const int y = blockIdx.y;
    const int b = blockIdx.z;

    const int base   = (blockIdx.x * WPB + wid) * PXW;      // warp's first x
    const int win_lo = min(max(base - 56, 0), W - WIN);      // %4 == 0 always

    const float* rowL = fea_l + (size_t)(b * C * H + y) * W;
    const float* rowR = fea_r + (size_t)(b * C * H + y) * W;

    // ---- per-pixel setup (2 px per lane: x = base+lane, base+32+lane) ----
    int   o0[2], o1[2], o2[2], o3[2];     // smem tap offsets (j - win_lo)
    int   g0[2], g1[2], g2[2], g3[2];     // global tap columns (fallback)
    float wfr[2];
    bool  inw[2], vM[2], v0[2], vP[2];

    const int ty = y >> 2, iy = y & 3;
    #pragma unroll
    for (int p = 0; p < 2; ++p) {
        const int x  = base + p * 32 + lane;
        const int tx = x >> 2, jx = x & 3;
        const int tb = b * 3 * Ht * Wt + ty * Wt + tx;
        const float d   = __ldg(tile_plane + tb);
        const float ddx = __ldg(tile_plane + tb + Ht * Wt);
        const float ddy = __ldg(tile_plane + tb + 2 * Ht * Wt);

        const float disp0 = d + ((float)iy - 1.5f) * ddy + ((float)jx - 1.5f) * ddx;
        const float xs0 = (float)x - disp0;
        const float xf  = floorf(xs0);
        wfr[p] = xs0 - xf;
        const int x00 = (int)xf;

        const int j0 = min(max(x00 - 1, 0), W - 1);
        const int j1 = min(max(x00,     0), W - 1);
        const int j2 = min(max(x00 + 1, 0), W - 1);
        const int j3 = min(max(x00 + 2, 0), W - 1);
        g0[p] = j0; g1[p] = j1; g2[p] = j2; g3[p] = j3;
        o0[p] = j0 - win_lo; o1[p] = j1 - win_lo;
        o2[p] = j2 - win_lo; o3[p] = j3 - win_lo;
        inw[p] = (j0 >= win_lo) && (j3 < win_lo + WIN);

        const float wm1 = (float)(W - 1);
        vM[p] = (xs0 + 1.0f >= 0.0f) && (xs0 + 1.0f <= wm1);
        v0[p] = (xs0        >= 0.0f) && (xs0        <= wm1);
        vP[p] = (xs0 - 1.0f >= 0.0f) && (xs0 - 1.0f <= wm1);
    }

    // ---- async pipeline ----
    const uint32_t sring = (uint32_t)__cvta_generic_to_shared(&ring[wid][0][0]);

    auto issue = [&](int ch) {
        const int slot = ch & (D - 1);
        const bool ok = (ch < C);
        const size_t coff = (size_t)ch * HW;
        const uint32_t sb = sring + slot * (STG * 4);
        // 128-float fea_r window: 32 lanes x 16B
        cp16(sb + 16 * lane, rowR + coff + win_lo + 4 * lane, ok);
        // 64-float fea_l segment: lanes 0..15 x 16B
        cp16(sb + WIN * 4 + 16 * lane, rowL + coff + base + 4 * lane, ok && (lane < 16));
        cp_commit();
    };

    #pragma unroll
    for (int s = 0; s < D - 1; ++s) issue(s);

    float aM[2] = {0.f, 0.f}, a0[2] = {0.f, 0.f}, aP[2] = {0.f, 0.f}, aA[2] = {0.f, 0.f};
    const float* fbR = rowR;   // current-channel row for the (never-taken) fallback

    #pragma unroll 4
    for (int c = 0; c < C; ++c) {
        cp_wait<D - 2>();      // stage c landed (this lane's copies)
        __syncwarp();          // all lanes' copies visible; prior-iter reads retired
        issue(c + D - 1);      // refill the slot freed at iteration c-1

        const float* ws = ring[wid][c & (D - 1)];
        const float* wl = ws + WIN;

        #pragma unroll
        for (int p = 0; p < 2; ++p) {
            const float fl = wl[p * 32 + lane];
            float r0, r1, r2, r3;
            if (inw[p]) {
                r0 = ws[o0[p]]; r1 = ws[o1[p]];
                r2 = ws[o2[p]]; r3 = ws[o3[p]];
            } else {           // pathological slope — exact fallback
                r0 = __ldg(fbR + g0[p]); r1 = __ldg(fbR + g1[p]);
                r2 = __ldg(fbR + g2[p]); r3 = __ldg(fbR + g3[p]);
            }
            const float w  = wfr[p];
            const float wP = fmaf(w, r1 - r0, r0);   // disp_d = +1
            const float w0 = fmaf(w, r2 - r1, r1);   // disp_d =  0
            const float wM = fmaf(w, r3 - r2, r2);   // disp_d = -1
            aM[p] += fabsf(fl - wM);
            a0[p] += fabsf(fl - w0);
            aP[p] += fabsf(fl - wP);
            aA[p] += fabsf(fl);
        }
        fbR += HW;
    }

    // ---- epilogue: apply validity, write [B,48,Ht,Wt] ----
    #pragma unroll
    for (int p = 0; p < 2; ++p) {
        const int x  = base + p * 32 + lane;
        const int tx = x >> 2, jx = x & 3;
        const float cM = vM[p] ? aM[p] : aA[p];
        const float c0 = v0[p] ? a0[p] : aA[p];
        const float cP = vP[p] ? aP[p] : aA[p];
        const int chsp  = (iy * 4 + jx) * (Ht * Wt);
        const int obase = b * 48 * Ht * Wt + ty * Wt + tx;
        out[obase + chsp]                = cM;   // disp_d = -1
        out[obase + 16 * Ht * Wt + chsp] = c0;   // disp_d =  0
        out[obase + 32 * Ht * Wt + chsp] = cP;   // disp_d = +1
    }
}

extern "C" void kernel_launch(void* const* d_in, const int* in_sizes, int n_in,
                              void* d_out, int out_size)
{
    const float* tile_plane = (const float*)d_in[0];
    const float* fea_l      = (const float*)d_in[1];
    const float* fea_r      = (const float*)d_in[2];
    float*       out        = (float*)d_out;

    dim3 grid(W / (WPB * PXW), H, NB);   // (3, 512, 4)
    dim3 block(32 * WPB);                // 160
    tile_warp_cost_kernel<<<grid, block>>>(tile_plane, fea_l, fea_r, out);
}

// round 4
// speedup vs baseline: 1.5315x; 1.3545x over previous
#include <cuda_runtime.h>

constexpr int NB = 4;
constexpr int C  = 32;
constexpr int H  = 512;
constexpr int W  = 960;
constexpr int Ht = 128;
constexpr int Wt = 240;
constexpr int HW = H * W;
constexpr int BX = 160;     // 960 = 6*160
constexpr int UB = 4;       // channel batch (loads in flight = 5*UB = 20)

__global__ __launch_bounds__(BX)
void tile_warp_cost_kernel(const float* __restrict__ tile_plane,
                           const float* __restrict__ fea_l,
                           const float* __restrict__ fea_r,
                           float* __restrict__ out)
{
    const int x = blockIdx.x * BX + threadIdx.x;   // 0..959
    const int y = blockIdx.y;                      // 0..511
    const int b = blockIdx.z;                      // 0..3

    const int ty = y >> 2, tx = x >> 2;
    const int iy = y & 3,  jx = x & 3;

    // tile_plane [B, 3, Ht, Wt]
    const int tbase = b * 3 * Ht * Wt + ty * Wt + tx;
    const float d   = __ldg(tile_plane + tbase);
    const float ddx = __ldg(tile_plane + tbase + Ht * Wt);
    const float ddy = __ldg(tile_plane + tbase + 2 * Ht * Wt);

    // disp_d = 0 slanted-plane disparity; all 3 hypotheses share the frac weight
    const float disp0 = d + ((float)iy - 1.5f) * ddy + ((float)jx - 1.5f) * ddx;
    const float xs0   = (float)x - disp0;
    const float xf    = floorf(xs0);
    const float w     = xs0 - xf;
    const int   x00   = (int)xf;

    // 4 shared (clamped) tap columns covering all three hypotheses
    const int j0 = min(max(x00 - 1, 0), W - 1);
    const int j1 = min(max(x00,     0), W - 1);
    const int j2 = min(max(x00 + 1, 0), W - 1);
    const int j3 = min(max(x00 + 2, 0), W - 1);

    const float* pl = fea_l + (size_t)(b * C * H + y) * W + x;
    const float* pr = fea_r + (size_t)(b * C * H + y) * W;

    float cM = 0.f, c0 = 0.f, cP = 0.f, sA = 0.f;

    #pragma unroll 1
    for (int cb = 0; cb < C; cb += UB) {
        float fl[UB], r0[UB], r1[UB], r2[UB], r3[UB];

        // ---- load phase: 5*UB independent LDGs issued back-to-back ----
        #pragma unroll
        for (int u = 0; u < UB; ++u) {
            const float* rr = pr + u * HW;
            fl[u] = __ldg(pl + u * HW);
            r0[u] = __ldg(rr + j0);
            r1[u] = __ldg(rr + j1);
            r2[u] = __ldg(rr + j2);
            r3[u] = __ldg(rr + j3);
        }

        // ---- compute phase ----
        #pragma unroll
        for (int u = 0; u < UB; ++u) {
            const float wP = fmaf(w, r1[u] - r0[u], r0[u]);  // disp_d = +1
            const float w0 = fmaf(w, r2[u] - r1[u], r1[u]);  // disp_d =  0
            const float wM = fmaf(w, r3[u] - r2[u], r2[u]);  // disp_d = -1
            cM += fabsf(fl[u] - wM);
            c0 += fabsf(fl[u] - w0);
            cP += fabsf(fl[u] - wP);
            sA += fabsf(fl[u]);                              // invalid-hyp fallback
        }
        pl += UB * HW;
        pr += UB * HW;
    }

    // per-pixel validity applied once at the end
    const float wm1 = (float)(W - 1);
    if (!((xs0 + 1.0f >= 0.0f) && (xs0 + 1.0f <= wm1))) cM = sA;  // disp_d = -1
    if (!((xs0        >= 0.0f) && (xs0        <= wm1))) c0 = sA;  // disp_d =  0
    if (!((xs0 - 1.0f >= 0.0f) && (xs0 - 1.0f <= wm1))) cP = sA;  // disp_d = +1

    // output [B, 48, Ht, Wt]; channel = vblock*16 + iy*4 + jx; vblocks: -1, 0, +1
    const int chsp  = (iy * 4 + jx) * (Ht * Wt);
    const int obase = b * 48 * Ht * Wt + ty * Wt + tx;
    out[obase + chsp]                = cM;
    out[obase + 16 * Ht * Wt + chsp] = c0;
    out[obase + 32 * Ht * Wt + chsp] = cP;
}

extern "C" void kernel_launch(void* const* d_in, const int* in_sizes, int n_in,
                              void* d_out, int out_size)
{
    const float* tile_plane = (const float*)d_in[0];
    const float* fea_l      = (const float*)d_in[1];
    const float* fea_r      = (const float*)d_in[2];
    float*       out        = (float*)d_out;

    dim3 grid(W / BX, H, NB);   // (6, 512, 4)
    dim3 block(BX);
    tile_warp_cost_kernel<<<grid, block>>>(tile_plane, fea_l, fea_r, out);
}